// round 5
// baseline (speedup 1.0000x reference)
#include <cuda_runtime.h>
#include <cuda_bf16.h>
#include <math.h>

// Problem constants
#define TT   4096
#define DD   2560
#define NH   8
#define KH   4
#define HD   256
#define WIN  1024

// ---------------- scratch (device globals; allocation-free rule) ----------------
__device__ float g_W[DD * 4096];        // packed [d][j] qkv weights: q(2048)|k(1024)|v(1024)
__device__ float g_QKV[TT * 4096];      // [t][j] projections; q,k normed+roped in place
__device__ float g_ENC[TT * 2048];      // [t][n*256+h] attention output
__device__ float g_SIN[TT * 128];
__device__ float g_COS[TT * 128];

// ---------------- weight pack ----------------
__global__ void pack_w_kernel(const float* __restrict__ qw,
                              const float* __restrict__ kvw,
                              float* __restrict__ W)
{
    int idx = blockIdx.x * blockDim.x + threadIdx.x;   // over 2560*4096
    int d = idx >> 12;
    int j = idx & 4095;
    float v;
    if (j < 2048) {
        int n = j >> 8, h = j & 255;
        v = qw[((size_t)n * DD + d) * HD + h];
    } else if (j < 3072) {
        int kk = (j - 2048) >> 8, h = j & 255;
        v = kvw[((size_t)kk * DD + d) * HD + h];
    } else {
        int kk = (j - 3072) >> 8, h = j & 255;
        v = kvw[((size_t)(4 + kk) * DD + d) * HD + h];
    }
    W[idx] = v;
}

// ---------------- rope table (double sin/cos, fp32 angle matching reference) ----------------
__global__ void rope_table_kernel(const int* __restrict__ positions,
                                  float* __restrict__ st, float* __restrict__ ct)
{
    int idx = blockIdx.x * blockDim.x + threadIdx.x;   // 4096*128
    int t = idx >> 7;
    int i = idx & 127;
    float posf = (float)positions[t];
    // timescale = 10000^(i/128) computed to fp32 (correctly rounded via double)
    float ts = (float)pow(10000.0, (double)i * (1.0 / 128.0));
    float ang = posf / ts;                  // fp32, like reference
    double s, c;
    sincos((double)ang, &s, &c);
    st[idx] = (float)s;
    ct[idx] = (float)c;
}

// ---------------- SGEMM 128x128x8, 256 threads, 8x8 per thread ----------------
__global__ __launch_bounds__(256, 2) void sgemm_kernel(
    const float* __restrict__ A0, const float* __restrict__ A1, int splitRow, int lda,
    const float* __restrict__ B, int ldb,
    float* __restrict__ C, int ldc, int Kd)
{
    __shared__ float As[8][128];
    __shared__ float Bs[8][128];
    const int tid  = threadIdx.x;
    const int brow = blockIdx.y * 128;
    const int bcol = blockIdx.x * 128;

    const int arow = tid >> 1;
    const int acol = (tid & 1) << 2;
    const int gr   = brow + arow;
    const float* Arow = (gr < splitRow) ? (A0 + (size_t)gr * lda)
                                        : (A1 + (size_t)(gr - splitRow) * lda);
    const int bro = tid >> 5;
    const int bco = (tid & 31) << 2;
    const float* Bptr = B + (size_t)bro * ldb + bcol + bco;

    const int tx = tid & 15;
    const int ty = tid >> 4;

    float acc[8][8];
#pragma unroll
    for (int i = 0; i < 8; i++)
#pragma unroll
        for (int j = 0; j < 8; j++) acc[i][j] = 0.f;

    for (int k0 = 0; k0 < Kd; k0 += 8) {
        float4 av = *(const float4*)(Arow + k0 + acol);
        float4 bv = *(const float4*)(Bptr + (size_t)k0 * ldb);
        As[acol + 0][arow] = av.x;
        As[acol + 1][arow] = av.y;
        As[acol + 2][arow] = av.z;
        As[acol + 3][arow] = av.w;
        *(float4*)&Bs[bro][bco] = bv;
        __syncthreads();
#pragma unroll
        for (int kk = 0; kk < 8; kk++) {
            float a[8], b[8];
            *(float4*)&a[0] = *(const float4*)&As[kk][ty * 8];
            *(float4*)&a[4] = *(const float4*)&As[kk][ty * 8 + 4];
            *(float4*)&b[0] = *(const float4*)&Bs[kk][tx * 8];
            *(float4*)&b[4] = *(const float4*)&Bs[kk][tx * 8 + 4];
#pragma unroll
            for (int i = 0; i < 8; i++)
#pragma unroll
                for (int j = 0; j < 8; j++) acc[i][j] += a[i] * b[j];
        }
        __syncthreads();
    }
#pragma unroll
    for (int i = 0; i < 8; i++) {
        float* Crow = C + (size_t)(brow + ty * 8 + i) * ldc + bcol + tx * 8;
        *(float4*)&Crow[0] = make_float4(acc[i][0], acc[i][1], acc[i][2], acc[i][3]);
        *(float4*)&Crow[4] = make_float4(acc[i][4], acc[i][5], acc[i][6], acc[i][7]);
    }
}

// ---------------- RMSNorm + RoPE (in place on q,k columns of g_QKV) ----------------
__global__ void norm_rope_kernel(float* __restrict__ qkv,
                                 const float* __restrict__ qns,
                                 const float* __restrict__ kns,
                                 const float* __restrict__ st,
                                 const float* __restrict__ ct)
{
    int t  = blockIdx.x;
    int hh = blockIdx.y;                 // 0..7 q heads, 8..11 k heads
    bool isq = hh < 8;
    int colbase = isq ? (hh << 8) : (2048 + ((hh - 8) << 8));
    const float* sc = isq ? qns : kns;
    float* row = qkv + (size_t)t * 4096 + colbase;
    int i = threadIdx.x;                 // 0..127
    float f = row[i];
    float s = row[i + 128];
    float ss = f * f + s * s;
#pragma unroll
    for (int off = 16; off; off >>= 1) ss += __shfl_xor_sync(0xffffffffu, ss, off);
    __shared__ float red[4];
    if ((i & 31) == 0) red[i >> 5] = ss;
    __syncthreads();
    float mean = (red[0] + red[1] + red[2] + red[3]) * (1.f / 256.f);
    float inv = (float)(1.0 / sqrt((double)mean + 1e-6));
    float fn = f * inv * (1.f + sc[i]);
    float sn = s * inv * (1.f + sc[i + 128]);
    float sa = st[(t << 7) + i];
    float ca = ct[(t << 7) + i];
    float o1 = fn * ca - sn * sa;
    float o2 = sn * ca + fn * sa;
    if (isq) { o1 *= 0.0625f; o2 *= 0.0625f; }   // H^-0.5 = 1/16
    row[i]       = o1;
    row[i + 128] = o2;
}

// ---------------- fused sliding-window flash attention ----------------
// grid (64 qtiles, 8 heads), 256 threads. BQ=64, BKV=64, 4x4 micro-tiles.
#define SQ_LD 260
#define SP_LD 66
#define ATTN_SMEM_FLOATS (64 * SQ_LD * 3 + 64 * SP_LD)

__global__ __launch_bounds__(256) void attn_kernel(const float* __restrict__ qkv,
                                                   float* __restrict__ enc)
{
    extern __shared__ float sm[];
    float* sQ = sm;
    float* sK = sQ + 64 * SQ_LD;
    float* sV = sK + 64 * SQ_LD;
    float* sP = sV + 64 * SQ_LD;

    const int qt0  = blockIdx.x << 6;
    const int n    = blockIdx.y;
    const int kvh  = n >> 1;
    const int qcol = n << 8;
    const int kcol = 2048 + (kvh << 8);
    const int vcol = 3072 + (kvh << 8);
    const int tid = threadIdx.x;
    const int tx = tid & 15;
    const int ty = tid >> 4;

    for (int idx = tid; idx < 64 * 64; idx += 256) {
        int r = idx >> 6, c4 = (idx & 63) << 2;
        *(float4*)&sQ[r * SQ_LD + c4] =
            *(const float4*)&qkv[(size_t)(qt0 + r) * 4096 + qcol + c4];
    }

    float m_[4], l_[4], O[4][16];
#pragma unroll
    for (int i = 0; i < 4; i++) {
        m_[i] = -1e30f; l_[i] = 0.f;
#pragma unroll
        for (int c = 0; c < 16; c++) O[i][c] = 0.f;
    }
    const int tg0 = qt0 + (ty << 2);

    int s_lo = qt0 - (WIN - 1); if (s_lo < 0) s_lo = 0;
    int ks0 = s_lo & ~63;

    for (int ks = ks0; ks < qt0 + 64; ks += 64) {
        __syncthreads();   // protect sK/sV/sP from previous iteration's readers
        for (int idx = tid; idx < 64 * 64; idx += 256) {
            int r = idx >> 6, c4 = (idx & 63) << 2;
            *(float4*)&sK[r * SQ_LD + c4] =
                *(const float4*)&qkv[(size_t)(ks + r) * 4096 + kcol + c4];
            *(float4*)&sV[r * SQ_LD + c4] =
                *(const float4*)&qkv[(size_t)(ks + r) * 4096 + vcol + c4];
        }
        __syncthreads();

        float S[4][4];
#pragma unroll
        for (int i = 0; i < 4; i++)
#pragma unroll
            for (int j = 0; j < 4; j++) S[i][j] = 0.f;

#pragma unroll 4
        for (int d = 0; d < 256; d += 4) {
            float4 aa[4], bb[4];
#pragma unroll
            for (int i = 0; i < 4; i++)
                aa[i] = *(const float4*)&sQ[(ty * 4 + i) * SQ_LD + d];
#pragma unroll
            for (int j = 0; j < 4; j++)
                bb[j] = *(const float4*)&sK[(tx * 4 + j) * SQ_LD + d];
#pragma unroll
            for (int i = 0; i < 4; i++)
#pragma unroll
                for (int j = 0; j < 4; j++)
                    S[i][j] += aa[i].x * bb[j].x + aa[i].y * bb[j].y +
                               aa[i].z * bb[j].z + aa[i].w * bb[j].w;
        }

        // mask + online softmax (row groups shared across the 16 tx lanes)
#pragma unroll
        for (int i = 0; i < 4; i++) {
            int tg = tg0 + i;
            float mx = -1e30f;
#pragma unroll
            for (int j = 0; j < 4; j++) {
                int sg = ks + (tx << 2) + j;
                if (sg > tg || sg + WIN <= tg) S[i][j] = -1e30f;
                mx = fmaxf(mx, S[i][j]);
            }
#pragma unroll
            for (int off = 8; off; off >>= 1)
                mx = fmaxf(mx, __shfl_xor_sync(0xffffffffu, mx, off));
            float mn = fmaxf(m_[i], mx);
            float alpha = expf(m_[i] - mn);
            float ps = 0.f;
#pragma unroll
            for (int j = 0; j < 4; j++) {
                float p = (S[i][j] > -1e29f) ? expf(S[i][j] - mn) : 0.f;
                sP[(ty * 4 + i) * SP_LD + (tx << 2) + j] = p;
                ps += p;
            }
#pragma unroll
            for (int off = 8; off; off >>= 1)
                ps += __shfl_xor_sync(0xffffffffu, ps, off);
            l_[i] = l_[i] * alpha + ps;
            m_[i] = mn;
#pragma unroll
            for (int c = 0; c < 16; c++) O[i][c] *= alpha;
        }
        __syncthreads();

        // PV: O[4][16] += P[4][64] @ V[64][16-slice]
#pragma unroll 2
        for (int kk = 0; kk < 64; kk++) {
            float pr[4];
#pragma unroll
            for (int i = 0; i < 4; i++) pr[i] = sP[(ty * 4 + i) * SP_LD + kk];
            const float* vr = &sV[kk * SQ_LD + (tx << 4)];
            float vv[16];
            *(float4*)&vv[0]  = *(const float4*)&vr[0];
            *(float4*)&vv[4]  = *(const float4*)&vr[4];
            *(float4*)&vv[8]  = *(const float4*)&vr[8];
            *(float4*)&vv[12] = *(const float4*)&vr[12];
#pragma unroll
            for (int i = 0; i < 4; i++)
#pragma unroll
                for (int c = 0; c < 16; c++) O[i][c] += pr[i] * vv[c];
        }
    }

    // epilogue: normalize and write enc[t][n*256 + h]
#pragma unroll
    for (int i = 0; i < 4; i++) {
        float invl = 1.f / l_[i];
        float* er = &enc[(size_t)(tg0 + i) * 2048 + (n << 8) + (tx << 4)];
#pragma unroll
        for (int c = 0; c < 16; c += 4)
            *(float4*)&er[c] = make_float4(O[i][c] * invl, O[i][c + 1] * invl,
                                           O[i][c + 2] * invl, O[i][c + 3] * invl);
    }
}

// ---------------- launch ----------------
extern "C" void kernel_launch(void* const* d_in, const int* in_sizes, int n_in,
                              void* d_out, int out_size)
{
    const float* x1   = (const float*)d_in[0];
    const float* x2   = (const float*)d_in[1];
    const float* qw   = (const float*)d_in[2];
    const float* kvw  = (const float*)d_in[3];
    const float* outw = (const float*)d_in[4];
    const float* qns  = (const float*)d_in[5];
    const float* kns  = (const float*)d_in[6];
    const int*   pos  = (const int*)d_in[7];
    float* out = (float*)d_out;

    float *pW, *pQKV, *pENC, *pSIN, *pCOS;
    cudaGetSymbolAddress((void**)&pW,   g_W);
    cudaGetSymbolAddress((void**)&pQKV, g_QKV);
    cudaGetSymbolAddress((void**)&pENC, g_ENC);
    cudaGetSymbolAddress((void**)&pSIN, g_SIN);
    cudaGetSymbolAddress((void**)&pCOS, g_COS);

    // 1) pack qkv weights into [d][4096]
    pack_w_kernel<<<(DD * 4096) / 256, 256>>>(qw, kvw, pW);
    // 2) rope sin/cos table
    rope_table_kernel<<<(TT * 128) / 256, 256>>>(pos, pSIN, pCOS);
    // 3) QKV projection: [4096,2560] @ [2560,4096]
    sgemm_kernel<<<dim3(4096 / 128, TT / 128), 256>>>(
        x1, x2, 2048, DD, pW, 4096, pQKV, 4096, DD);
    // 4) RMSNorm + RoPE in place
    norm_rope_kernel<<<dim3(TT, 12), 128>>>(pQKV, qns, kns, pSIN, pCOS);
    // 5) sliding-window flash attention
    size_t smem = ATTN_SMEM_FLOATS * sizeof(float);
    cudaFuncSetAttribute(attn_kernel, cudaFuncAttributeMaxDynamicSharedMemorySize, (int)smem);
    attn_kernel<<<dim3(TT / 64, NH), 256, smem>>>(pQKV, pENC);
    // 6) output projection: [4096,2048] @ [2048,2560] -> d_out
    sgemm_kernel<<<dim3(DD / 128, TT / 128), 256>>>(
        pENC, pENC, TT, 2048, outw, DD, out, DD, 2048);
}